// round 2
// baseline (speedup 1.0000x reference)
#include <cuda_runtime.h>
#include <math.h>

#define NSEQ 2048
#define HDIM 1024
#define NHEAD 16
#define DH 64
#define S2 1024        // 2 * span
#define SPAN 512
#define INV_SCALE 0.0721687836487032f   // 1/sqrt(64*3)

// ---------------- scratch (device globals; no allocations allowed) ----------
__device__ float g_Q[NHEAD * NSEQ * DH];
__device__ float g_K[NHEAD * NSEQ * DH];
__device__ float g_V[NHEAD * NSEQ * DH];
__device__ float g_PosK[NHEAD * S2 * DH];
__device__ float g_PosQ[NHEAD * S2 * DH];
__device__ float g_c2p[(size_t)NHEAD * NSEQ * S2];   // 134 MB
__device__ float g_p2c[(size_t)NHEAD * NSEQ * S2];   // 134 MB

// ---------------------------------------------------------------------------
// NT GEMM core: C[m][n] = sum_k A[m][k] * B[n][k]
// BM=128, BN=128, BK=16, 256 threads, per-thread tile 8 x 8.
// ---------------------------------------------------------------------------
__device__ __forceinline__ void gemm_nt_body(const float* __restrict__ A,
                                             const float* __restrict__ B,
                                             int K, int lda, int ldb,
                                             int m0, int n0,
                                             float (&acc)[8][8]) {
    __shared__ float As[16][132];
    __shared__ float Bs[16][132];
    const int t  = threadIdx.x;
    const int ty = t >> 4;
    const int tx = t & 15;

#pragma unroll
    for (int i = 0; i < 8; i++)
#pragma unroll
        for (int j = 0; j < 8; j++) acc[i][j] = 0.0f;

    for (int kt = 0; kt < K; kt += 16) {
#pragma unroll
        for (int i = 0; i < 8; i++) {
            int lin = i * 256 + t;
            int r = lin >> 4, c = lin & 15;
            As[c][r] = A[(m0 + r) * lda + kt + c];
        }
#pragma unroll
        for (int i = 0; i < 8; i++) {
            int lin = i * 256 + t;
            int r = lin >> 4, c = lin & 15;
            Bs[c][r] = B[(n0 + r) * ldb + kt + c];
        }
        __syncthreads();
#pragma unroll
        for (int kk = 0; kk < 16; kk++) {
            float a[8], b[8];
            *(float4*)&a[0] = *(const float4*)&As[kk][ty * 8];
            *(float4*)&a[4] = *(const float4*)&As[kk][ty * 8 + 4];
            *(float4*)&b[0] = *(const float4*)&Bs[kk][tx * 8];
            *(float4*)&b[4] = *(const float4*)&Bs[kk][tx * 8 + 4];
#pragma unroll
            for (int i = 0; i < 8; i++)
#pragma unroll
                for (int j = 0; j < 8; j++)
                    acc[i][j] = fmaf(a[i], b[j], acc[i][j]);
        }
        __syncthreads();
    }
}

// ---------------------------------------------------------------------------
// K1: fused QKV projection
// ---------------------------------------------------------------------------
__global__ void __launch_bounds__(256) qkv_kernel(const float* __restrict__ hidden,
                                                  const float* __restrict__ W,
                                                  const float* __restrict__ qb,
                                                  const float* __restrict__ vb) {
    float acc[8][8];
    const int m0 = blockIdx.y * 128;
    const int n0 = blockIdx.x * 128;
    gemm_nt_body(hidden, W, HDIM, HDIM, HDIM, m0, n0, acc);
    const int ty = threadIdx.x >> 4, tx = threadIdx.x & 15;
#pragma unroll
    for (int i = 0; i < 8; i++) {
        int m = m0 + ty * 8 + i;
#pragma unroll
        for (int j = 0; j < 8; j++) {
            int cg = n0 + tx * 8 + j;
            int h  = cg / 192;
            int jj = cg - h * 192;
            float val = acc[i][j];
            if (jj < 64)
                g_Q[(h * NSEQ + m) * DH + jj] = (val + qb[h * 64 + jj]) * INV_SCALE;
            else if (jj < 128)
                g_K[(h * NSEQ + m) * DH + (jj - 64)] = val;
            else
                g_V[(h * NSEQ + m) * DH + (jj - 128)] = val + vb[h * 64 + (jj - 128)];
        }
    }
}

// ---------------------------------------------------------------------------
// K2: position projections
// ---------------------------------------------------------------------------
__global__ void __launch_bounds__(256) pos_kernel(const float* __restrict__ rel,
                                                  const float* __restrict__ W,
                                                  const float* __restrict__ bias,
                                                  int which) {
    float acc[8][8];
    const int m0 = blockIdx.y * 128;   // s
    const int n0 = blockIdx.x * 128;   // c
    gemm_nt_body(rel, W, HDIM, HDIM, HDIM, m0, n0, acc);
    const int ty = threadIdx.x >> 4, tx = threadIdx.x & 15;
#pragma unroll
    for (int i = 0; i < 8; i++) {
        int s = m0 + ty * 8 + i;
#pragma unroll
        for (int j = 0; j < 8; j++) {
            int c = n0 + tx * 8 + j;
            int h = c >> 6, d = c & 63;
            if (which == 0)
                g_PosK[(h * S2 + s) * DH + d] = acc[i][j];
            else
                g_PosQ[(h * S2 + s) * DH + d] = (acc[i][j] + bias[c]) * INV_SCALE;
        }
    }
}

// ---------------------------------------------------------------------------
// K3: raw relative scores; z = h + 16*which
// ---------------------------------------------------------------------------
__global__ void __launch_bounds__(256) relsc_kernel() {
    const int z  = blockIdx.z;
    const int h  = z & 15;
    const int which = z >> 4;
    const int m0 = blockIdx.y * 128;
    const int n0 = blockIdx.x * 128;
    const float* A = (which == 0 ? g_Q : g_K) + h * NSEQ * DH;
    const float* B = (which == 0 ? g_PosK : g_PosQ) + h * S2 * DH;
    float* O = (which == 0 ? g_c2p : g_p2c);
    float acc[8][8];
    gemm_nt_body(A, B, DH, DH, DH, m0, n0, acc);
    const int ty = threadIdx.x >> 4, tx = threadIdx.x & 15;
#pragma unroll
    for (int i = 0; i < 8; i++) {
        int m = m0 + ty * 8 + i;
#pragma unroll
        for (int j = 0; j < 8; j++) {
            int n = n0 + tx * 8 + j;
            O[((size_t)(h * NSEQ + m)) * S2 + n] = acc[i][j];
        }
    }
}

// ---------------------------------------------------------------------------
// K4: fused flash attention: S = QK^T + c2p + p2c (gathered), masked online
// softmax, O = P V, output transpose. One block per (q-tile=128, head).
// smem: Qs[64][132] | Ks[64][132] | Vs[128][68] | Ps[128][132]   ~166 KB
// ---------------------------------------------------------------------------
#define QS_OFF 0
#define KS_OFF (64 * 132)
#define VS_OFF (KS_OFF + 64 * 132)
#define PS_OFF (VS_OFF + 128 * 68)
#define FLASH_SMEM ((PS_OFF + 128 * 132) * 4)

__global__ void __launch_bounds__(256, 1) flash_kernel(const int* __restrict__ mask,
                                                       float* __restrict__ out) {
    extern __shared__ float sm[];
    float* Qs = sm + QS_OFF;   // [d][m] 64 x 132
    float* Ks = sm + KS_OFF;   // [d][n] 64 x 132
    float* Vs = sm + VS_OFF;   // [k][d] 128 x 68
    float* Ps = sm + PS_OFF;   // [m][k] 128 x 132

    const int h  = blockIdx.y;
    const int q0 = blockIdx.x * 128;
    const int t  = threadIdx.x;
    const int ty = t >> 4;
    const int tx = t & 15;

    // load Q tile once: Qs[d][m] = g_Q[(h*NSEQ + q0+m)*64 + d]
    {
        const float* Qg = g_Q + (size_t)(h * NSEQ + q0) * DH;
#pragma unroll
        for (int it = 0; it < 8; it++) {
            int lin = (it * 256 + t) * 4;        // float4 granularity
            int m = lin >> 6, d = lin & 63;
            float4 v = *(const float4*)&Qg[m * DH + d];
            Qs[(d + 0) * 132 + m] = v.x;
            Qs[(d + 1) * 132 + m] = v.y;
            Qs[(d + 2) * 132 + m] = v.z;
            Qs[(d + 3) * 132 + m] = v.w;
        }
    }

    float m_i[8], l_i[8], O[8][4];
#pragma unroll
    for (int i = 0; i < 8; i++) {
        m_i[i] = -INFINITY; l_i[i] = 0.0f;
#pragma unroll
        for (int j = 0; j < 4; j++) O[i][j] = 0.0f;
    }

    const float* Kg = g_K + (size_t)h * NSEQ * DH;
    const float* Vg = g_V + (size_t)h * NSEQ * DH;
    const float* C2 = g_c2p + (size_t)h * NSEQ * S2;
    const float* P2 = g_p2c + (size_t)h * NSEQ * S2;

    for (int kt = 0; kt < NSEQ / 128; kt++) {
        const int k0 = kt * 128;
        __syncthreads();   // prev PV done before overwriting Ks/Vs
        // load K tile -> Ks[d][n], V tile -> Vs[k][d]
#pragma unroll
        for (int it = 0; it < 8; it++) {
            int lin = (it * 256 + t) * 4;
            int n = lin >> 6, d = lin & 63;
            float4 v = *(const float4*)&Kg[(k0 + n) * DH + d];
            Ks[(d + 0) * 132 + n] = v.x;
            Ks[(d + 1) * 132 + n] = v.y;
            Ks[(d + 2) * 132 + n] = v.z;
            Ks[(d + 3) * 132 + n] = v.w;
            float4 w = *(const float4*)&Vg[(k0 + n) * DH + d];
            *(float4*)&Vs[n * 68 + d] = w;
        }
        __syncthreads();

        // S = Q K^T  (8x8 per thread)
        float acc[8][8];
#pragma unroll
        for (int i = 0; i < 8; i++)
#pragma unroll
            for (int j = 0; j < 8; j++) acc[i][j] = 0.0f;
#pragma unroll
        for (int kk = 0; kk < DH; kk++) {
            float a[8], b[8];
            *(float4*)&a[0] = *(const float4*)&Qs[kk * 132 + ty * 8];
            *(float4*)&a[4] = *(const float4*)&Qs[kk * 132 + ty * 8 + 4];
            *(float4*)&b[0] = *(const float4*)&Ks[kk * 132 + tx * 8];
            *(float4*)&b[4] = *(const float4*)&Ks[kk * 132 + tx * 8 + 4];
#pragma unroll
            for (int i = 0; i < 8; i++)
#pragma unroll
                for (int j = 0; j < 8; j++)
                    acc[i][j] = fmaf(a[i], b[j], acc[i][j]);
        }

        // add disentangled biases + mask
#pragma unroll
        for (int i = 0; i < 8; i++) {
            const int q = q0 + ty * 8 + i;
#pragma unroll
            for (int j = 0; j < 8; j++) {
                const int kc = k0 + tx * 8 + j;
                int idx = q - kc + SPAN;
                idx = idx < 0 ? 0 : (idx > S2 - 1 ? S2 - 1 : idx);
                float val = acc[i][j]
                          + __ldg(&C2[(size_t)q * S2 + idx])
                          + __ldg(&P2[(size_t)kc * S2 + idx]);
                if (__ldg(&mask[q * NSEQ + kc]) == 0) val = -1e30f;
                acc[i][j] = val;
            }
        }

        // online softmax: per-row stats over 16 tx lanes (within half-warp)
        float scale_i[8];
#pragma unroll
        for (int i = 0; i < 8; i++) {
            float mx = acc[i][0];
#pragma unroll
            for (int j = 1; j < 8; j++) mx = fmaxf(mx, acc[i][j]);
#pragma unroll
            for (int o = 8; o > 0; o >>= 1)
                mx = fmaxf(mx, __shfl_xor_sync(0xffffffffu, mx, o));
            float mnew = fmaxf(m_i[i], mx);
            scale_i[i] = __expf(m_i[i] - mnew);
            float s = 0.0f;
#pragma unroll
            for (int j = 0; j < 8; j++) {
                acc[i][j] = __expf(acc[i][j] - mnew);
                s += acc[i][j];
            }
#pragma unroll
            for (int o = 8; o > 0; o >>= 1)
                s += __shfl_xor_sync(0xffffffffu, s, o);
            l_i[i] = l_i[i] * scale_i[i] + s;
            m_i[i] = mnew;
#pragma unroll
            for (int j = 0; j < 4; j++) O[i][j] *= scale_i[i];
        }

        __syncthreads();   // Ps reads from prev iter done (covered by top sync) / writers ready
        // store P -> Ps[m][k]
#pragma unroll
        for (int i = 0; i < 8; i++) {
            float4 v0 = make_float4(acc[i][0], acc[i][1], acc[i][2], acc[i][3]);
            float4 v1 = make_float4(acc[i][4], acc[i][5], acc[i][6], acc[i][7]);
            *(float4*)&Ps[(ty * 8 + i) * 132 + tx * 8]     = v0;
            *(float4*)&Ps[(ty * 8 + i) * 132 + tx * 8 + 4] = v1;
        }
        __syncthreads();

        // O += P V : process 4 k at a time
#pragma unroll
        for (int kq = 0; kq < 32; kq++) {
            float4 b0 = *(const float4*)&Vs[(kq * 4 + 0) * 68 + tx * 4];
            float4 b1 = *(const float4*)&Vs[(kq * 4 + 1) * 68 + tx * 4];
            float4 b2 = *(const float4*)&Vs[(kq * 4 + 2) * 68 + tx * 4];
            float4 b3 = *(const float4*)&Vs[(kq * 4 + 3) * 68 + tx * 4];
#pragma unroll
            for (int i = 0; i < 8; i++) {
                float4 a = *(const float4*)&Ps[(ty * 8 + i) * 132 + kq * 4];
                O[i][0] = fmaf(a.x, b0.x, O[i][0]);
                O[i][1] = fmaf(a.x, b0.y, O[i][1]);
                O[i][2] = fmaf(a.x, b0.z, O[i][2]);
                O[i][3] = fmaf(a.x, b0.w, O[i][3]);
                O[i][0] = fmaf(a.y, b1.x, O[i][0]);
                O[i][1] = fmaf(a.y, b1.y, O[i][1]);
                O[i][2] = fmaf(a.y, b1.z, O[i][2]);
                O[i][3] = fmaf(a.y, b1.w, O[i][3]);
                O[i][0] = fmaf(a.z, b2.x, O[i][0]);
                O[i][1] = fmaf(a.z, b2.y, O[i][1]);
                O[i][2] = fmaf(a.z, b2.z, O[i][2]);
                O[i][3] = fmaf(a.z, b2.w, O[i][3]);
                O[i][0] = fmaf(a.w, b3.x, O[i][0]);
                O[i][1] = fmaf(a.w, b3.y, O[i][1]);
                O[i][2] = fmaf(a.w, b3.z, O[i][2]);
                O[i][3] = fmaf(a.w, b3.w, O[i][3]);
            }
        }
    }

    // epilogue: normalize + write out[q][h*64 + d]
#pragma unroll
    for (int i = 0; i < 8; i++) {
        float inv = 1.0f / l_i[i];
        int q = q0 + ty * 8 + i;
        float4 v = make_float4(O[i][0] * inv, O[i][1] * inv, O[i][2] * inv, O[i][3] * inv);
        *(float4*)&out[(size_t)q * HDIM + h * DH + tx * 4] = v;
    }
}

// ---------------------------------------------------------------------------
extern "C" void kernel_launch(void* const* d_in, const int* in_sizes, int n_in,
                              void* d_out, int out_size) {
    const float* hidden   = (const float*)d_in[0];
    const int*   mask     = (const int*)  d_in[1];
    const float* rel_emb  = (const float*)d_in[3];
    const float* in_proj  = (const float*)d_in[4];
    const float* q_bias   = (const float*)d_in[5];
    const float* v_bias   = (const float*)d_in[6];
    const float* pos_w    = (const float*)d_in[7];
    const float* pos_q_w  = (const float*)d_in[8];
    const float* pos_q_b  = (const float*)d_in[9];
    float* out = (float*)d_out;

    cudaFuncSetAttribute(flash_kernel, cudaFuncAttributeMaxDynamicSharedMemorySize,
                         FLASH_SMEM);

    // K1: QKV projection  (M=2048, N=3072, K=1024)
    qkv_kernel<<<dim3(3072 / 128, 2048 / 128), 256>>>(hidden, in_proj, q_bias, v_bias);

    // K2: position projections (M=1024, N=1024, K=1024) x2
    pos_kernel<<<dim3(HDIM / 128, S2 / 128), 256>>>(rel_emb, pos_w,   pos_q_b, 0);
    pos_kernel<<<dim3(HDIM / 128, S2 / 128), 256>>>(rel_emb, pos_q_w, pos_q_b, 1);

    // K3: c2p_raw / p2c_raw  (per head/which: M=2048, N=1024, K=64)
    relsc_kernel<<<dim3(S2 / 128, NSEQ / 128, NHEAD * 2), 256>>>();

    // K4: fused flash attention
    flash_kernel<<<dim3(NSEQ / 128, NHEAD), 256, FLASH_SMEM>>>(mask, out);
}

// round 3
// speedup vs baseline: 1.2377x; 1.2377x over previous
#include <cuda_runtime.h>
#include <math.h>

#define NSEQ 2048
#define HDIM 1024
#define NHEAD 16
#define DH 64
#define S2 1024        // 2 * span
#define SPAN 512
#define INV_SCALE 0.0721687836487032f   // 1/sqrt(64*3)

// ---------------- scratch (device globals; no allocations allowed) ----------
__device__ float g_Q[NHEAD * NSEQ * DH];
__device__ float g_K[NHEAD * NSEQ * DH];
__device__ float g_V[NHEAD * NSEQ * DH];
__device__ float g_PosK[NHEAD * S2 * DH];
__device__ float g_PosQ[NHEAD * S2 * DH];
__device__ float g_c2p[(size_t)NHEAD * NSEQ * S2];   // 134 MB
__device__ float g_p2c[(size_t)NHEAD * NSEQ * S2];   // 134 MB
__device__ float g_sc [(size_t)NHEAD * NSEQ * NSEQ]; // 268 MB raw masked scores
__device__ float g_rowM  [NHEAD * NSEQ];             // per-row max
__device__ float g_rowInv[NHEAD * NSEQ];             // per-row 1/sum(exp)

// ------------------------------- cp.async ----------------------------------
__device__ __forceinline__ unsigned smem_u32(const void* p) {
    return (unsigned)__cvta_generic_to_shared(p);
}
#define CP_ASYNC4(dst, src) \
    asm volatile("cp.async.ca.shared.global [%0], [%1], 4;" :: "r"(dst), "l"(src))
#define CP_COMMIT() asm volatile("cp.async.commit_group;")
#define CP_WAIT1()  asm volatile("cp.async.wait_group 1;")
#define CP_WAIT0()  asm volatile("cp.async.wait_group 0;")

// ---------------------------------------------------------------------------
// Double-buffered NT GEMM core: C[m][n] = sum_k A[m][k] * B[n][k]
// BM=128, BN=128, BK=16, 256 threads, per-thread tile 8x8.
// ---------------------------------------------------------------------------
__device__ __forceinline__ void gemm_nt_db(const float* __restrict__ A,
                                           const float* __restrict__ B,
                                           int K, int lda, int ldb,
                                           int m0, int n0,
                                           float (&acc)[8][8]) {
    __shared__ float As[2][16][132];
    __shared__ float Bs[2][16][132];
    const int t  = threadIdx.x;
    const int ty = t >> 4;
    const int tx = t & 15;

#pragma unroll
    for (int i = 0; i < 8; i++)
#pragma unroll
        for (int j = 0; j < 8; j++) acc[i][j] = 0.0f;

    const int c  = t & 15;         // k-offset within tile
    const int r0 = t >> 4;         // base row (step 16)

    // issue loads for tile starting at column kt into buffer buf
    auto issue = [&](int kt, int buf) {
#pragma unroll
        for (int i = 0; i < 8; i++) {
            int r = i * 16 + r0;
            CP_ASYNC4(smem_u32(&As[buf][c][r]), &A[(size_t)(m0 + r) * lda + kt + c]);
        }
#pragma unroll
        for (int i = 0; i < 8; i++) {
            int r = i * 16 + r0;
            CP_ASYNC4(smem_u32(&Bs[buf][c][r]), &B[(size_t)(n0 + r) * ldb + kt + c]);
        }
        CP_COMMIT();
    };

    const int nt = K >> 4;
    issue(0, 0);
    for (int kt = 0; kt < nt; kt++) {
        const int buf = kt & 1;
        if (kt + 1 < nt) { issue((kt + 1) << 4, buf ^ 1); CP_WAIT1(); }
        else             { CP_WAIT0(); }
        __syncthreads();
#pragma unroll
        for (int kk = 0; kk < 16; kk++) {
            float a[8], b[8];
            *(float4*)&a[0] = *(const float4*)&As[buf][kk][ty * 8];
            *(float4*)&a[4] = *(const float4*)&As[buf][kk][ty * 8 + 4];
            *(float4*)&b[0] = *(const float4*)&Bs[buf][kk][tx * 8];
            *(float4*)&b[4] = *(const float4*)&Bs[buf][kk][tx * 8 + 4];
#pragma unroll
            for (int i = 0; i < 8; i++)
#pragma unroll
                for (int j = 0; j < 8; j++)
                    acc[i][j] = fmaf(a[i], b[j], acc[i][j]);
        }
        __syncthreads();
    }
}

// ---------------------------------------------------------------------------
// K1: fused QKV projection
// ---------------------------------------------------------------------------
__global__ void __launch_bounds__(256) qkv_kernel(const float* __restrict__ hidden,
                                                  const float* __restrict__ W,
                                                  const float* __restrict__ qb,
                                                  const float* __restrict__ vb) {
    float acc[8][8];
    const int m0 = blockIdx.y * 128;
    const int n0 = blockIdx.x * 128;
    gemm_nt_db(hidden, W, HDIM, HDIM, HDIM, m0, n0, acc);
    const int ty = threadIdx.x >> 4, tx = threadIdx.x & 15;
#pragma unroll
    for (int i = 0; i < 8; i++) {
        int m = m0 + ty * 8 + i;
#pragma unroll
        for (int j = 0; j < 8; j++) {
            int cg = n0 + tx * 8 + j;
            int h  = cg / 192;
            int jj = cg - h * 192;
            float val = acc[i][j];
            if (jj < 64)
                g_Q[(h * NSEQ + m) * DH + jj] = (val + qb[h * 64 + jj]) * INV_SCALE;
            else if (jj < 128)
                g_K[(h * NSEQ + m) * DH + (jj - 64)] = val;
            else
                g_V[(h * NSEQ + m) * DH + (jj - 128)] = val + vb[h * 64 + (jj - 128)];
        }
    }
}

// ---------------------------------------------------------------------------
// K2: position projections; z=0: PosK, z=1: PosQ
// ---------------------------------------------------------------------------
__global__ void __launch_bounds__(256) pos_kernel(const float* __restrict__ rel,
                                                  const float* __restrict__ Wk,
                                                  const float* __restrict__ Wq,
                                                  const float* __restrict__ bias) {
    const int which = blockIdx.z;
    float acc[8][8];
    const int m0 = blockIdx.y * 128;   // s
    const int n0 = blockIdx.x * 128;   // c
    gemm_nt_db(rel, which == 0 ? Wk : Wq, HDIM, HDIM, HDIM, m0, n0, acc);
    const int ty = threadIdx.x >> 4, tx = threadIdx.x & 15;
#pragma unroll
    for (int i = 0; i < 8; i++) {
        int s = m0 + ty * 8 + i;
#pragma unroll
        for (int j = 0; j < 8; j++) {
            int cc = n0 + tx * 8 + j;
            int h = cc >> 6, d = cc & 63;
            if (which == 0)
                g_PosK[(h * S2 + s) * DH + d] = acc[i][j];
            else
                g_PosQ[(h * S2 + s) * DH + d] = (acc[i][j] + bias[cc]) * INV_SCALE;
        }
    }
}

// ---------------------------------------------------------------------------
// K3: raw relative scores; z = h + 16*which
// ---------------------------------------------------------------------------
__global__ void __launch_bounds__(256) relsc_kernel() {
    const int z     = blockIdx.z;
    const int h     = z & 15;
    const int which = z >> 4;
    const int m0 = blockIdx.y * 128;
    const int n0 = blockIdx.x * 128;
    const float* A = (which == 0 ? g_Q : g_K) + h * NSEQ * DH;
    const float* B = (which == 0 ? g_PosK : g_PosQ) + h * S2 * DH;
    float* O = (which == 0 ? g_c2p : g_p2c);
    float acc[8][8];
    gemm_nt_db(A, B, DH, DH, DH, m0, n0, acc);
    const int ty = threadIdx.x >> 4, tx = threadIdx.x & 15;
#pragma unroll
    for (int i = 0; i < 8; i++) {
        int m = m0 + ty * 8 + i;
#pragma unroll
        for (int j = 0; j < 8; j++) {
            int n = n0 + tx * 8 + j;
            O[((size_t)(h * NSEQ + m)) * S2 + n] = acc[i][j];
        }
    }
}

// ---------------------------------------------------------------------------
// K4: content-content scores + fused gathers + mask -> raw masked scores
// ---------------------------------------------------------------------------
__global__ void __launch_bounds__(256) scores_kernel(const int* __restrict__ mask) {
    const int h  = blockIdx.z;
    const int m0 = blockIdx.y * 128;
    const int n0 = blockIdx.x * 128;
    float acc[8][8];
    gemm_nt_db(g_Q + h * NSEQ * DH, g_K + h * NSEQ * DH, DH, DH, DH, m0, n0, acc);
    const int ty = threadIdx.x >> 4, tx = threadIdx.x & 15;
    const float* C2 = g_c2p + (size_t)h * NSEQ * S2;
    const float* P2 = g_p2c + (size_t)h * NSEQ * S2;
#pragma unroll
    for (int i = 0; i < 8; i++) {
        int q = m0 + ty * 8 + i;
#pragma unroll
        for (int j = 0; j < 8; j++) {
            int kc = n0 + tx * 8 + j;
            int idx = q - kc + SPAN;
            idx = idx < 0 ? 0 : (idx > S2 - 1 ? S2 - 1 : idx);
            float val = acc[i][j]
                      + __ldg(&C2[(size_t)q * S2 + idx])
                      + __ldg(&P2[(size_t)kc * S2 + idx]);
            if (__ldg(&mask[q * NSEQ + kc]) == 0) val = -1e30f;
            g_sc[((size_t)(h * NSEQ + q)) * NSEQ + kc] = val;
        }
    }
}

// ---------------------------------------------------------------------------
// K5: per-row max and 1/sum(exp) (no rewrite of scores)
// ---------------------------------------------------------------------------
__global__ void __launch_bounds__(256) rowstat_kernel() {
    const int row = blockIdx.x;              // h*NSEQ + q
    const size_t base = (size_t)row * NSEQ;
    const int t = threadIdx.x;
    __shared__ float red[16];

    float v[8];
    float mx = -INFINITY;
#pragma unroll
    for (int i = 0; i < 8; i++) {
        v[i] = g_sc[base + t + i * 256];
        mx = fmaxf(mx, v[i]);
    }
#pragma unroll
    for (int o = 16; o > 0; o >>= 1) mx = fmaxf(mx, __shfl_xor_sync(0xffffffffu, mx, o));
    if ((t & 31) == 0) red[t >> 5] = mx;
    __syncthreads();
    float rowmax = red[0];
#pragma unroll
    for (int i = 1; i < 8; i++) rowmax = fmaxf(rowmax, red[i]);

    float s = 0.0f;
#pragma unroll
    for (int i = 0; i < 8; i++) s += __expf(v[i] - rowmax);
#pragma unroll
    for (int o = 16; o > 0; o >>= 1) s += __shfl_xor_sync(0xffffffffu, s, o);
    if ((t & 31) == 0) red[8 + (t >> 5)] = s;
    __syncthreads();
    if (t == 0) {
        float tot = 0.0f;
#pragma unroll
        for (int i = 0; i < 8; i++) tot += red[8 + i];
        g_rowM[row]   = rowmax;
        g_rowInv[row] = 1.0f / tot;
    }
}

// ---------------------------------------------------------------------------
// K6: ctx = softmax(P) @ V  with exp/normalize fused into the A-tile load.
// BM=128, BN=64, BK=16. Masked entries (-1e30) -> expf underflows to 0.
// ---------------------------------------------------------------------------
__global__ void __launch_bounds__(256) pv_kernel(float* __restrict__ out) {
    const int h  = blockIdx.z;
    const int m0 = blockIdx.y * 128;
    const float* A = g_sc + (size_t)h * NSEQ * NSEQ;
    const float* B = g_V + h * NSEQ * DH;

    __shared__ float As[16][132];
    __shared__ float Bs[16][68];
    __shared__ float rowm[128], rowi[128];
    const int t  = threadIdx.x;
    const int ty = t >> 4;
    const int tx = t & 15;

    if (t < 128) {
        rowm[t] = g_rowM[h * NSEQ + m0 + t];
        rowi[t] = g_rowInv[h * NSEQ + m0 + t];
    }
    __syncthreads();

    float acc[8][4];
#pragma unroll
    for (int i = 0; i < 8; i++)
#pragma unroll
        for (int j = 0; j < 4; j++) acc[i][j] = 0.0f;

    for (int kt = 0; kt < NSEQ; kt += 16) {
#pragma unroll
        for (int i = 0; i < 8; i++) {
            int lin = i * 256 + t;
            int r = lin >> 4, c = lin & 15;
            float raw = A[(size_t)(m0 + r) * NSEQ + kt + c];
            As[c][r] = __expf(raw - rowm[r]) * rowi[r];
        }
#pragma unroll
        for (int i = 0; i < 4; i++) {
            int lin = i * 256 + t;
            int kr = lin >> 6, nc = lin & 63;
            Bs[kr][nc] = B[(kt + kr) * DH + nc];
        }
        __syncthreads();
#pragma unroll
        for (int kk = 0; kk < 16; kk++) {
            float a[8], b[4];
            *(float4*)&a[0] = *(const float4*)&As[kk][ty * 8];
            *(float4*)&a[4] = *(const float4*)&As[kk][ty * 8 + 4];
            *(float4*)&b[0] = *(const float4*)&Bs[kk][tx * 4];
#pragma unroll
            for (int i = 0; i < 8; i++)
#pragma unroll
                for (int j = 0; j < 4; j++)
                    acc[i][j] = fmaf(a[i], b[j], acc[i][j]);
        }
        __syncthreads();
    }

    // write out[q][h*64 + d]
#pragma unroll
    for (int i = 0; i < 8; i++) {
        int m = m0 + ty * 8 + i;
        float4 v = make_float4(acc[i][0], acc[i][1], acc[i][2], acc[i][3]);
        *(float4*)&out[(size_t)m * HDIM + h * DH + tx * 4] = v;
    }
}

// ---------------------------------------------------------------------------
extern "C" void kernel_launch(void* const* d_in, const int* in_sizes, int n_in,
                              void* d_out, int out_size) {
    const float* hidden   = (const float*)d_in[0];
    const int*   mask     = (const int*)  d_in[1];
    const float* rel_emb  = (const float*)d_in[3];
    const float* in_proj  = (const float*)d_in[4];
    const float* q_bias   = (const float*)d_in[5];
    const float* v_bias   = (const float*)d_in[6];
    const float* pos_w    = (const float*)d_in[7];
    const float* pos_q_w  = (const float*)d_in[8];
    const float* pos_q_b  = (const float*)d_in[9];
    float* out = (float*)d_out;

    // K1: QKV projection  (M=2048, N=3072, K=1024)
    qkv_kernel<<<dim3(3072 / 128, 2048 / 128), 256>>>(hidden, in_proj, q_bias, v_bias);

    // K2: position projections (M=1024, N=1024, K=1024), z = which
    pos_kernel<<<dim3(HDIM / 128, S2 / 128, 2), 256>>>(rel_emb, pos_w, pos_q_w, pos_q_b);

    // K3: c2p_raw / p2c_raw  (per head/which: M=2048, N=1024, K=64)
    relsc_kernel<<<dim3(S2 / 128, NSEQ / 128, NHEAD * 2), 256>>>();

    // K4: scores = QK^T + c2p + p2c, masked
    scores_kernel<<<dim3(NSEQ / 128, NSEQ / 128, NHEAD), 256>>>(mask);

    // K5: row stats
    rowstat_kernel<<<NHEAD * NSEQ, 256>>>();

    // K6: probs @ V + output transpose  (per head: M=2048, N=64, K=2048)
    pv_kernel<<<dim3(1, NSEQ / 128, NHEAD), 256>>>(out);
}

// round 4
// speedup vs baseline: 2.6003x; 2.1009x over previous
#include <cuda_runtime.h>
#include <math.h>

#define NSEQ 2048
#define HDIM 1024
#define NHEAD 16
#define DH 64
#define S2 1024        // 2 * span
#define SPAN 512
#define INV_SCALE 0.0721687836487032f   // 1/sqrt(64*3)

// ---------------- scratch (device globals; no allocations allowed) ----------
__device__ float g_Q[NHEAD * NSEQ * DH];
__device__ float g_K[NHEAD * NSEQ * DH];
__device__ float g_V[NHEAD * NSEQ * DH];
__device__ float g_PosK[NHEAD * S2 * DH];
__device__ float g_PosQ[NHEAD * S2 * DH];
__device__ float g_c2p[(size_t)NHEAD * NSEQ * S2];   // 134 MB
__device__ float g_p2c[(size_t)NHEAD * NSEQ * S2];   // 134 MB
__device__ float g_sc [(size_t)NHEAD * NSEQ * NSEQ]; // 268 MB raw masked scores
__device__ float g_rowM  [NHEAD * NSEQ];
__device__ float g_rowInv[NHEAD * NSEQ];
__device__ float g_pvp[(size_t)4 * NHEAD * NSEQ * DH]; // split-K partials (134 MB)

// ------------------------------- tf32 mma -----------------------------------
__device__ __forceinline__ unsigned f2tf(float x) {
    unsigned r;
    asm("cvt.rna.tf32.f32 %0, %1;" : "=r"(r) : "f"(x));
    return r;
}

__device__ __forceinline__ void mma_tf32(float (&d)[4],
                                         unsigned a0, unsigned a1, unsigned a2, unsigned a3,
                                         unsigned b0, unsigned b1) {
    asm volatile(
        "mma.sync.aligned.m16n8k8.row.col.f32.tf32.tf32.f32 "
        "{%0,%1,%2,%3}, {%4,%5,%6,%7}, {%8,%9}, {%0,%1,%2,%3};"
        : "+f"(d[0]), "+f"(d[1]), "+f"(d[2]), "+f"(d[3])
        : "r"(a0), "r"(a1), "r"(a2), "r"(a3), "r"(b0), "r"(b1));
}

// One BK=16 step. As layout [k][m] (ldsa), Bs layout [k][n] (ldsb), values
// already tf32-converted bit patterns stored as float.
template <int MT, int NT>
__device__ __forceinline__ void mma_bk16(const float* __restrict__ As, int ldsa,
                                         const float* __restrict__ Bs, int ldsb,
                                         int wm0, int wn0, int lane,
                                         float (&acc)[MT][NT][4]) {
    const int kq = lane & 3, rq = lane >> 2;
#pragma unroll
    for (int s = 0; s < 2; s++) {
        const int k0 = s * 8 + kq;
        unsigned a[MT][4];
#pragma unroll
        for (int mt = 0; mt < MT; mt++) {
            const int m = wm0 + mt * 16 + rq;
            a[mt][0] = __float_as_uint(As[k0 * ldsa + m]);
            a[mt][1] = __float_as_uint(As[k0 * ldsa + m + 8]);
            a[mt][2] = __float_as_uint(As[(k0 + 4) * ldsa + m]);
            a[mt][3] = __float_as_uint(As[(k0 + 4) * ldsa + m + 8]);
        }
#pragma unroll
        for (int nt = 0; nt < NT; nt++) {
            const int n = wn0 + nt * 8 + rq;
            unsigned b0 = __float_as_uint(Bs[k0 * ldsb + n]);
            unsigned b1 = __float_as_uint(Bs[(k0 + 4) * ldsb + n]);
#pragma unroll
            for (int mt = 0; mt < MT; mt++)
                mma_tf32(acc[mt][nt], a[mt][0], a[mt][1], a[mt][2], a[mt][3], b0, b1);
        }
    }
}

// ---------------------------------------------------------------------------
// K1: QKV projection. M=2048, N=3072, K=1024. BM=BN=128, BK=16, double-buffered.
// ---------------------------------------------------------------------------
__global__ void __launch_bounds__(256) qkv_kernel(const float* __restrict__ hidden,
                                                  const float* __restrict__ W,
                                                  const float* __restrict__ qb,
                                                  const float* __restrict__ vb) {
    __shared__ float As[2][16 * 132];
    __shared__ float Bs[2][16 * 132];
    const int t = threadIdx.x, lane = t & 31, wid = t >> 5;
    const int wm0 = (wid >> 1) * 32, wn0 = (wid & 1) * 64;
    const int m0 = blockIdx.y * 128, n0 = blockIdx.x * 128;
    const int r0 = t >> 2, g = t & 3;

    float acc[2][8][4];
#pragma unroll
    for (int mt = 0; mt < 2; mt++)
#pragma unroll
        for (int nt = 0; nt < 8; nt++)
#pragma unroll
            for (int e = 0; e < 4; e++) acc[mt][nt][e] = 0.0f;

    float4 ra[2], rb[2];
    auto ldg = [&](int kt) {
        ra[0] = *(const float4*)&hidden[(size_t)(m0 + r0) * HDIM + kt + g * 4];
        ra[1] = *(const float4*)&hidden[(size_t)(m0 + r0 + 64) * HDIM + kt + g * 4];
        rb[0] = *(const float4*)&W[(size_t)(n0 + r0) * HDIM + kt + g * 4];
        rb[1] = *(const float4*)&W[(size_t)(n0 + r0 + 64) * HDIM + kt + g * 4];
    };
    auto sts = [&](int buf) {
        const float* pa = (const float*)ra;
        const float* pb = (const float*)rb;
#pragma unroll
        for (int half = 0; half < 2; half++) {
            int r = r0 + half * 64;
#pragma unroll
            for (int e = 0; e < 4; e++) {
                As[buf][(g * 4 + e) * 132 + r] = __uint_as_float(f2tf(pa[half * 4 + e]));
                Bs[buf][(g * 4 + e) * 132 + r] = __uint_as_float(f2tf(pb[half * 4 + e]));
            }
        }
    };

    ldg(0); sts(0);
    const int nt_tiles = HDIM / 16;
    for (int kt = 0; kt < nt_tiles; kt++) {
        __syncthreads();
        if (kt + 1 < nt_tiles) ldg((kt + 1) * 16);
        mma_bk16<2, 8>(As[kt & 1], 132, Bs[kt & 1], 132, wm0, wn0, lane, acc);
        if (kt + 1 < nt_tiles) sts((kt + 1) & 1);
    }

    const int kq = lane & 3, rq = lane >> 2;
#pragma unroll
    for (int mt = 0; mt < 2; mt++)
#pragma unroll
        for (int nt = 0; nt < 8; nt++)
#pragma unroll
            for (int h2 = 0; h2 < 2; h2++) {
                int m  = m0 + wm0 + mt * 16 + rq + h2 * 8;
                int cg = n0 + wn0 + nt * 8 + kq * 2;
                int head = cg / 192;
                int jj = cg - head * 192;
                float v0 = acc[mt][nt][h2 * 2], v1 = acc[mt][nt][h2 * 2 + 1];
                if (jj < 64) {
                    v0 = (v0 + qb[head * 64 + jj]) * INV_SCALE;
                    v1 = (v1 + qb[head * 64 + jj + 1]) * INV_SCALE;
                    *(float2*)&g_Q[(size_t)(head * NSEQ + m) * DH + jj] = make_float2(v0, v1);
                } else if (jj < 128) {
                    *(float2*)&g_K[(size_t)(head * NSEQ + m) * DH + jj - 64] = make_float2(v0, v1);
                } else {
                    v0 += vb[head * 64 + jj - 128];
                    v1 += vb[head * 64 + jj - 127];
                    *(float2*)&g_V[(size_t)(head * NSEQ + m) * DH + jj - 128] = make_float2(v0, v1);
                }
            }
}

// ---------------------------------------------------------------------------
// K2: position projections. z=0: PosK, z=1: PosQ. M=N=K=1024.
// ---------------------------------------------------------------------------
__global__ void __launch_bounds__(256) pos_kernel(const float* __restrict__ rel,
                                                  const float* __restrict__ Wk,
                                                  const float* __restrict__ Wq,
                                                  const float* __restrict__ bias) {
    __shared__ float As[2][16 * 132];
    __shared__ float Bs[2][16 * 132];
    const int which = blockIdx.z;
    const float* W = which == 0 ? Wk : Wq;
    const int t = threadIdx.x, lane = t & 31, wid = t >> 5;
    const int wm0 = (wid >> 1) * 32, wn0 = (wid & 1) * 64;
    const int m0 = blockIdx.y * 128, n0 = blockIdx.x * 128;
    const int r0 = t >> 2, g = t & 3;

    float acc[2][8][4];
#pragma unroll
    for (int mt = 0; mt < 2; mt++)
#pragma unroll
        for (int nt = 0; nt < 8; nt++)
#pragma unroll
            for (int e = 0; e < 4; e++) acc[mt][nt][e] = 0.0f;

    float4 ra[2], rb[2];
    auto ldg = [&](int kt) {
        ra[0] = *(const float4*)&rel[(size_t)(m0 + r0) * HDIM + kt + g * 4];
        ra[1] = *(const float4*)&rel[(size_t)(m0 + r0 + 64) * HDIM + kt + g * 4];
        rb[0] = *(const float4*)&W[(size_t)(n0 + r0) * HDIM + kt + g * 4];
        rb[1] = *(const float4*)&W[(size_t)(n0 + r0 + 64) * HDIM + kt + g * 4];
    };
    auto sts = [&](int buf) {
        const float* pa = (const float*)ra;
        const float* pb = (const float*)rb;
#pragma unroll
        for (int half = 0; half < 2; half++) {
            int r = r0 + half * 64;
#pragma unroll
            for (int e = 0; e < 4; e++) {
                As[buf][(g * 4 + e) * 132 + r] = __uint_as_float(f2tf(pa[half * 4 + e]));
                Bs[buf][(g * 4 + e) * 132 + r] = __uint_as_float(f2tf(pb[half * 4 + e]));
            }
        }
    };

    ldg(0); sts(0);
    const int nt_tiles = HDIM / 16;
    for (int kt = 0; kt < nt_tiles; kt++) {
        __syncthreads();
        if (kt + 1 < nt_tiles) ldg((kt + 1) * 16);
        mma_bk16<2, 8>(As[kt & 1], 132, Bs[kt & 1], 132, wm0, wn0, lane, acc);
        if (kt + 1 < nt_tiles) sts((kt + 1) & 1);
    }

    const int kq = lane & 3, rq = lane >> 2;
#pragma unroll
    for (int mt = 0; mt < 2; mt++)
#pragma unroll
        for (int nt = 0; nt < 8; nt++)
#pragma unroll
            for (int h2 = 0; h2 < 2; h2++) {
                int s  = m0 + wm0 + mt * 16 + rq + h2 * 8;
                int cc = n0 + wn0 + nt * 8 + kq * 2;
                int head = cc >> 6, d = cc & 63;
                float v0 = acc[mt][nt][h2 * 2], v1 = acc[mt][nt][h2 * 2 + 1];
                if (which == 0) {
                    *(float2*)&g_PosK[(size_t)(head * S2 + s) * DH + d] = make_float2(v0, v1);
                } else {
                    v0 = (v0 + bias[cc]) * INV_SCALE;
                    v1 = (v1 + bias[cc + 1]) * INV_SCALE;
                    *(float2*)&g_PosQ[(size_t)(head * S2 + s) * DH + d] = make_float2(v0, v1);
                }
            }
}

// ---------------------------------------------------------------------------
// Shared fill for K=64 single-shot tiles: [128 rows x 64 k] -> T[k][m] (pad 132)
// ---------------------------------------------------------------------------
__device__ __forceinline__ void fill_k64(const float* __restrict__ src, int row0,
                                         float* __restrict__ Ts, int t) {
#pragma unroll
    for (int i = 0; i < 8; i++) {
        int lin4 = i * 256 + t;           // 2048 float4s
        int r = lin4 >> 4, g = lin4 & 15;
        float4 v = *(const float4*)&src[(size_t)(row0 + r) * DH + g * 4];
        Ts[(g * 4 + 0) * 132 + r] = __uint_as_float(f2tf(v.x));
        Ts[(g * 4 + 1) * 132 + r] = __uint_as_float(f2tf(v.y));
        Ts[(g * 4 + 2) * 132 + r] = __uint_as_float(f2tf(v.z));
        Ts[(g * 4 + 3) * 132 + r] = __uint_as_float(f2tf(v.w));
    }
}

// ---------------------------------------------------------------------------
// K3: raw relative scores. z = h + 16*which. M=128-tile of 2048, N=128-tile of
// 1024, K=64 single-shot.
// ---------------------------------------------------------------------------
__global__ void __launch_bounds__(256) relsc_kernel() {
    extern __shared__ float sm[];
    float* As = sm;
    float* Bs = sm + 64 * 132;
    const int z = blockIdx.z;
    const int h = z & 15, which = z >> 4;
    const int m0 = blockIdx.y * 128, n0 = blockIdx.x * 128;
    const float* A = (which == 0 ? g_Q : g_K) + (size_t)h * NSEQ * DH;
    const float* B = (which == 0 ? g_PosK : g_PosQ) + (size_t)h * S2 * DH;
    float* O = (which == 0 ? g_c2p : g_p2c);

    const int t = threadIdx.x, lane = t & 31, wid = t >> 5;
    const int wm0 = (wid >> 1) * 32, wn0 = (wid & 1) * 64;

    fill_k64(A, m0, As, t);
    fill_k64(B, n0, Bs, t);
    __syncthreads();

    float acc[2][8][4];
#pragma unroll
    for (int mt = 0; mt < 2; mt++)
#pragma unroll
        for (int nt = 0; nt < 8; nt++)
#pragma unroll
            for (int e = 0; e < 4; e++) acc[mt][nt][e] = 0.0f;

#pragma unroll
    for (int s16 = 0; s16 < 4; s16++)
        mma_bk16<2, 8>(As + s16 * 16 * 132, 132, Bs + s16 * 16 * 132, 132,
                       wm0, wn0, lane, acc);

    const int kq = lane & 3, rq = lane >> 2;
#pragma unroll
    for (int mt = 0; mt < 2; mt++)
#pragma unroll
        for (int nt = 0; nt < 8; nt++)
#pragma unroll
            for (int h2 = 0; h2 < 2; h2++) {
                int m = m0 + wm0 + mt * 16 + rq + h2 * 8;
                int n = n0 + wn0 + nt * 8 + kq * 2;
                *(float2*)&O[((size_t)(h * NSEQ + m)) * S2 + n] =
                    make_float2(acc[mt][nt][h2 * 2], acc[mt][nt][h2 * 2 + 1]);
            }
}

// ---------------------------------------------------------------------------
// K4: scores = QK^T + c2p + p2c (smem-staged, coalesced) + mask.
// ---------------------------------------------------------------------------
__global__ void __launch_bounds__(256) scores_kernel(const int* __restrict__ mask) {
    extern __shared__ float sm[];
    float* As   = sm;                    // 64 x 132
    float* Bs   = sm + 64 * 132;         // 64 x 132
    float* c2pS = sm + 2 * 64 * 132;     // 128 x 132  [q-local][k-local]
    float* p2cT = c2pS + 128 * 132;      // 128 x 132  [q-local][k-local]

    const int h  = blockIdx.z;
    const int m0 = blockIdx.y * 128, n0 = blockIdx.x * 128;
    const int t = threadIdx.x, lane = t & 31, wid = t >> 5;
    const int wm0 = (wid >> 1) * 32, wn0 = (wid & 1) * 64;

    fill_k64(g_Q + (size_t)h * NSEQ * DH, m0, As, t);
    fill_k64(g_K + (size_t)h * NSEQ * DH, n0, Bs, t);

    const float* C2 = g_c2p + (size_t)h * NSEQ * S2;
    const float* P2 = g_p2c + (size_t)h * NSEQ * S2;
    // c2p tile: row r=q-local, coalesced along j (k-local)
#pragma unroll
    for (int i = 0; i < 64; i++) {
        int lin = i * 256 + t;           // 16384
        int r = lin >> 7, j = lin & 127;
        int q = m0 + r, kc = n0 + j;
        int idx = q - kc + SPAN;
        idx = idx < 0 ? 0 : (idx > S2 - 1 ? S2 - 1 : idx);
        c2pS[r * 132 + j] = C2[(size_t)q * S2 + idx];
    }
    // p2c tile: fill along q (coalesced in global), store transposed [q][k]
#pragma unroll
    for (int i = 0; i < 64; i++) {
        int lin = i * 256 + t;
        int jr = lin >> 7, qi = lin & 127;    // jr = k-local row, qi = q-local
        int kc = n0 + jr, q = m0 + qi;
        int idx = q - kc + SPAN;
        idx = idx < 0 ? 0 : (idx > S2 - 1 ? S2 - 1 : idx);
        p2cT[qi * 132 + jr] = P2[(size_t)kc * S2 + idx];
    }
    __syncthreads();

    float acc[2][8][4];
#pragma unroll
    for (int mt = 0; mt < 2; mt++)
#pragma unroll
        for (int nt = 0; nt < 8; nt++)
#pragma unroll
            for (int e = 0; e < 4; e++) acc[mt][nt][e] = 0.0f;

#pragma unroll
    for (int s16 = 0; s16 < 4; s16++)
        mma_bk16<2, 8>(As + s16 * 16 * 132, 132, Bs + s16 * 16 * 132, 132,
                       wm0, wn0, lane, acc);

    const int kq = lane & 3, rq = lane >> 2;
#pragma unroll
    for (int mt = 0; mt < 2; mt++)
#pragma unroll
        for (int nt = 0; nt < 8; nt++)
#pragma unroll
            for (int h2 = 0; h2 < 2; h2++) {
                int rm = wm0 + mt * 16 + rq + h2 * 8;   // q-local
                int rn = wn0 + nt * 8 + kq * 2;         // k-local
                int q = m0 + rm, kc = n0 + rn;
                float2 cb = *(const float2*)&c2pS[rm * 132 + rn];
                float2 pb = *(const float2*)&p2cT[rm * 132 + rn];
                int2 mk = *(const int2*)&mask[(size_t)q * NSEQ + kc];
                float v0 = acc[mt][nt][h2 * 2]     + cb.x + pb.x;
                float v1 = acc[mt][nt][h2 * 2 + 1] + cb.y + pb.y;
                if (mk.x == 0) v0 = -1e30f;
                if (mk.y == 0) v1 = -1e30f;
                *(float2*)&g_sc[((size_t)(h * NSEQ + q)) * NSEQ + kc] = make_float2(v0, v1);
            }
}

// ---------------------------------------------------------------------------
// K5: per-row max and 1/sum(exp)
// ---------------------------------------------------------------------------
__global__ void __launch_bounds__(256) rowstat_kernel() {
    const int row = blockIdx.x;
    const size_t base = (size_t)row * NSEQ;
    const int t = threadIdx.x;
    __shared__ float red[16];

    float v[8];
    float mx = -INFINITY;
#pragma unroll
    for (int i = 0; i < 8; i++) {
        v[i] = g_sc[base + t + i * 256];
        mx = fmaxf(mx, v[i]);
    }
#pragma unroll
    for (int o = 16; o > 0; o >>= 1) mx = fmaxf(mx, __shfl_xor_sync(0xffffffffu, mx, o));
    if ((t & 31) == 0) red[t >> 5] = mx;
    __syncthreads();
    float rowmax = red[0];
#pragma unroll
    for (int i = 1; i < 8; i++) rowmax = fmaxf(rowmax, red[i]);

    float s = 0.0f;
#pragma unroll
    for (int i = 0; i < 8; i++) s += __expf(v[i] - rowmax);
#pragma unroll
    for (int o = 16; o > 0; o >>= 1) s += __shfl_xor_sync(0xffffffffu, s, o);
    if ((t & 31) == 0) red[8 + (t >> 5)] = s;
    __syncthreads();
    if (t == 0) {
        float tot = 0.0f;
#pragma unroll
        for (int i = 0; i < 8; i++) tot += red[8 + i];
        g_rowM[row]   = rowmax;
        g_rowInv[row] = 1.0f / tot;
    }
}

// ---------------------------------------------------------------------------
// K6: split-K PV. grid (m-tiles=16, heads=16, kz=4). BM=128, BN=64, BK=16.
// exp/normalize fused into A fill. Partials to g_pvp.
// ---------------------------------------------------------------------------
__global__ void __launch_bounds__(256) pv_kernel() {
    __shared__ float As[2][16 * 132];
    __shared__ float Bs[2][16 * 68];
    __shared__ float rowm[128], rowi[128];

    const int mt0 = blockIdx.x, h = blockIdx.y, kz = blockIdx.z;
    const int m0 = mt0 * 128;
    const int kbase = kz * (NSEQ / 4);
    const int t = threadIdx.x, lane = t & 31, wid = t >> 5;
    const int wm0 = wid * 16;   // 8 warps x 16 rows
    const float* Ag = g_sc + (size_t)h * NSEQ * NSEQ;
    const float* Vg = g_V + (size_t)h * NSEQ * DH;

    if (t < 128) {
        rowm[t] = g_rowM[h * NSEQ + m0 + t];
        rowi[t] = g_rowInv[h * NSEQ + m0 + t];
    }
    __syncthreads();

    float acc[1][8][4];
#pragma unroll
    for (int nt = 0; nt < 8; nt++)
#pragma unroll
        for (int e = 0; e < 4; e++) acc[0][nt][e] = 0.0f;

    const int ra0 = t >> 2, ga = t & 3;     // A: 128 rows x 4 f4/row per 2 passes
    const int rb0 = t >> 4, gb = t & 15;    // B: 16 rows x 16 f4/row
    float4 pa[2], pb;
    auto ldg = [&](int kt) {
        pa[0] = *(const float4*)&Ag[(size_t)(m0 + ra0) * NSEQ + kbase + kt + ga * 4];
        pa[1] = *(const float4*)&Ag[(size_t)(m0 + ra0 + 64) * NSEQ + kbase + kt + ga * 4];
        pb    = *(const float4*)&Vg[(size_t)(kbase + kt + rb0) * DH + gb * 4];
    };
    auto sts = [&](int buf) {
#pragma unroll
        for (int half = 0; half < 2; half++) {
            int r = ra0 + half * 64;
            float m = rowm[r], iv = rowi[r];
            const float* p = (const float*)&pa[half];
#pragma unroll
            for (int e = 0; e < 4; e++) {
                float prob = __expf(p[e] - m) * iv;
                As[buf][(ga * 4 + e) * 132 + r] = __uint_as_float(f2tf(prob));
            }
        }
        const float* q = (const float*)&pb;
#pragma unroll
        for (int e = 0; e < 4; e++)
            Bs[buf][rb0 * 68 + gb * 4 + e] = __uint_as_float(f2tf(q[e]));
    };

    ldg(0); sts(0);
    const int ntile = (NSEQ / 4) / 16;   // 32
    for (int kt = 0; kt < ntile; kt++) {
        __syncthreads();
        if (kt + 1 < ntile) ldg((kt + 1) * 16);
        mma_bk16<1, 8>(As[kt & 1], 132, Bs[kt & 1], 68, wm0, 0, lane, acc);
        if (kt + 1 < ntile) sts((kt + 1) & 1);
    }

    const int kq = lane & 3, rq = lane >> 2;
    float* P = g_pvp + ((size_t)(kz * NHEAD + h) * NSEQ) * DH;
#pragma unroll
    for (int nt = 0; nt < 8; nt++)
#pragma unroll
        for (int h2 = 0; h2 < 2; h2++) {
            int m = m0 + wm0 + rq + h2 * 8;
            int n = nt * 8 + kq * 2;
            *(float2*)&P[(size_t)m * DH + n] =
                make_float2(acc[0][nt][h2 * 2], acc[0][nt][h2 * 2 + 1]);
        }
}

// ---------------------------------------------------------------------------
// K7: reduce split-K partials into output [m][h*64+d]
// ---------------------------------------------------------------------------
__global__ void __launch_bounds__(256) reduce_kernel(float* __restrict__ out) {
    int gid = blockIdx.x * 256 + threadIdx.x;   // over 2048*1024
    int m = gid >> 10;
    int c = gid & 1023;
    int h = c >> 6, d = c & 63;
    float s = 0.0f;
#pragma unroll
    for (int z = 0; z < 4; z++)
        s += g_pvp[((size_t)(z * NHEAD + h) * NSEQ + m) * DH + d];
    out[gid] = s;
}

// ---------------------------------------------------------------------------
extern "C" void kernel_launch(void* const* d_in, const int* in_sizes, int n_in,
                              void* d_out, int out_size) {
    const float* hidden   = (const float*)d_in[0];
    const int*   mask     = (const int*)  d_in[1];
    const float* rel_emb  = (const float*)d_in[3];
    const float* in_proj  = (const float*)d_in[4];
    const float* q_bias   = (const float*)d_in[5];
    const float* v_bias   = (const float*)d_in[6];
    const float* pos_w    = (const float*)d_in[7];
    const float* pos_q_w  = (const float*)d_in[8];
    const float* pos_q_b  = (const float*)d_in[9];
    float* out = (float*)d_out;

    const int relsc_smem  = 2 * 64 * 132 * 4;                    // 67584
    const int scores_smem = (2 * 64 * 132 + 2 * 128 * 132) * 4;  // 202752
    cudaFuncSetAttribute(relsc_kernel, cudaFuncAttributeMaxDynamicSharedMemorySize,
                         relsc_smem);
    cudaFuncSetAttribute(scores_kernel, cudaFuncAttributeMaxDynamicSharedMemorySize,
                         scores_smem);

    // K1: QKV projection
    qkv_kernel<<<dim3(3072 / 128, 2048 / 128), 256>>>(hidden, in_proj, q_bias, v_bias);

    // K2: position projections
    pos_kernel<<<dim3(HDIM / 128, S2 / 128, 2), 256>>>(rel_emb, pos_w, pos_q_w, pos_q_b);

    // K3: c2p_raw / p2c_raw
    relsc_kernel<<<dim3(S2 / 128, NSEQ / 128, NHEAD * 2), 256, relsc_smem>>>();

    // K4: scores
    scores_kernel<<<dim3(NSEQ / 128, NSEQ / 128, NHEAD), 256, scores_smem>>>(mask);

    // K5: row stats
    rowstat_kernel<<<NHEAD * NSEQ, 256>>>();

    // K6: split-K PV
    pv_kernel<<<dim3(NSEQ / 128, NHEAD, 4), 256>>>();

    // K7: reduce
    reduce_kernel<<<(NSEQ * HDIM) / 256, 256>>>(out);
}